// round 1
// baseline (speedup 1.0000x reference)
#include <cuda_runtime.h>
#include <math.h>

#define Bz 64
#define Sz 256
#define Ez 512
#define Hz 1024
#define G4 4096   // 4*Hz
#define Dz 512
#define Cz 2

// ---------------- device scratch (no cudaMalloc allowed) ----------------
__device__ float g_xw[(size_t)Sz * Bz * G4];   // [t*B + b][4H] precomputed x@Wx + bias
__device__ float g_h0[Hz * Bz];                // h transposed [H][B], ping
__device__ float g_h1[Hz * Bz];                // pong
__device__ float g_c[Hz * Bz];                 // cell state transposed [H][B]
__device__ float g_final[Bz * Hz];             // h at t = seq_len-1, [b][h]
__device__ float g_dense[Bz * Dz];             // relu(final @ dense_w + b)

// ---------------- init: zero h0 and c ----------------
__global__ void init_kernel() {
    int i = blockIdx.x * blockDim.x + threadIdx.x;
    if (i < Hz * Bz) { g_h0[i] = 0.f; g_c[i] = 0.f; }
}

// ---------------- xw = emb(X) @ W_x + bias ----------------
// M = S*B = 16384 (m = s*64 + b), N = 4096, K = 512.
// 128x128 block tile, BK=8, 256 threads, 8x8 microtile.
__global__ __launch_bounds__(256, 1) void xw_gemm(
    const int* __restrict__ X, const float* __restrict__ emb,
    const float* __restrict__ Wf, const float* __restrict__ bias)
{
    __shared__ float As[8][128];   // As[k][m]
    __shared__ float Bs[8][128];   // Bs[k][n]
    __shared__ int rows[128];

    const int tid = threadIdx.x;
    const int m0 = blockIdx.y * 128;
    const int n0 = blockIdx.x * 128;

    if (tid < 128) {
        int m = m0 + tid;                 // m = s*64 + b
        rows[tid] = X[(m & 63) * Sz + (m >> 6)];
    }
    __syncthreads();

    float acc[8][8];
#pragma unroll
    for (int i = 0; i < 8; i++)
#pragma unroll
        for (int j = 0; j < 8; j++) acc[i][j] = 0.f;

    const int ty = tid >> 4;          // 0..15 -> rows ty*8
    const int tx = tid & 15;          // 0..15 -> cols tx*8
    const int am  = tid & 127;        // A-load row
    const int ak4 = (tid >> 7) * 4;   // A-load k offset (0 or 4)
    const int bk  = tid >> 5;         // B-load k (0..7)
    const int bn  = (tid & 31) * 4;   // B-load n offset

    for (int kt = 0; kt < Ez; kt += 8) {
        float4 av = *(const float4*)(emb + (size_t)rows[am] * Ez + kt + ak4);
        As[ak4 + 0][am] = av.x;
        As[ak4 + 1][am] = av.y;
        As[ak4 + 2][am] = av.z;
        As[ak4 + 3][am] = av.w;
        *(float4*)&Bs[bk][bn] = *(const float4*)(Wf + (size_t)(kt + bk) * G4 + n0 + bn);
        __syncthreads();

#pragma unroll
        for (int k = 0; k < 8; k++) {
            float4 a0 = *(float4*)&As[k][ty * 8];
            float4 a1 = *(float4*)&As[k][ty * 8 + 4];
            float4 b0 = *(float4*)&Bs[k][tx * 8];
            float4 b1 = *(float4*)&Bs[k][tx * 8 + 4];
            float aa[8] = {a0.x, a0.y, a0.z, a0.w, a1.x, a1.y, a1.z, a1.w};
            float bb[8] = {b0.x, b0.y, b0.z, b0.w, b1.x, b1.y, b1.z, b1.w};
#pragma unroll
            for (int i = 0; i < 8; i++)
#pragma unroll
                for (int j = 0; j < 8; j++) acc[i][j] += aa[i] * bb[j];
        }
        __syncthreads();
    }

    // epilogue: + bias, store
    float4 bv0 = *(const float4*)(bias + n0 + tx * 8);
    float4 bv1 = *(const float4*)(bias + n0 + tx * 8 + 4);
#pragma unroll
    for (int i = 0; i < 8; i++) {
        size_t base = (size_t)(m0 + ty * 8 + i) * G4 + n0 + tx * 8;
        float4 o0 = make_float4(acc[i][0] + bv0.x, acc[i][1] + bv0.y,
                                acc[i][2] + bv0.z, acc[i][3] + bv0.w);
        float4 o1 = make_float4(acc[i][4] + bv1.x, acc[i][5] + bv1.y,
                                acc[i][6] + bv1.z, acc[i][7] + bv1.w);
        *(float4*)(g_xw + base)     = o0;
        *(float4*)(g_xw + base + 4) = o1;
    }
}

__device__ __forceinline__ float sigm(float x) { return 1.f / (1.f + expf(-x)); }

// ---------------- one LSTM step ----------------
// gates[b][n] = xw[t][b][n] + sum_k h[k][b] * Wh[k][n]   (h transposed [H][B])
// block owns 8 h-columns -> 32 gate columns (i,j,f,o for those h-cols).
// 128 blocks x 128 threads; 64x32 tile, 4x4 microtile, BK=16.
__global__ __launch_bounds__(128, 2) void step_kernel(
    const float* __restrict__ Wh,      // lstm_kernel + 512*4096
    const int* __restrict__ seqlen, int t)
{
    const float* h_in  = (t & 1) ? g_h1 : g_h0;
    float*       h_out = (t & 1) ? g_h0 : g_h1;
    const float* xw_t  = g_xw + (size_t)t * Bz * G4;

    __shared__ float Hs[16][64];   // Hs[k][b]
    __shared__ float Ws[16][32];   // Ws[k][j], j = gate*8 + (col-c0)
    __shared__ float Gs[64][32];   // gates tile for pointwise

    const int tid = threadIdx.x;
    const int c0  = blockIdx.x * 8;       // h-column base
    const int ty  = tid >> 3;             // 0..15 -> rows ty*4
    const int tx  = tid & 7;              // 0..7  -> cols tx*4

    // W-load mapping: 4 floats/thread/tile
    const int wk = tid >> 3;              // 0..15
    const int wj = (tid & 7) * 4;         // 0,4,...,28
    const int wg = wj >> 3;               // gate index
    const int wc = wj & 7;                // 0 or 4

    float acc[4][4];
#pragma unroll
    for (int i = 0; i < 4; i++)
#pragma unroll
        for (int j = 0; j < 4; j++) acc[i][j] = 0.f;

    for (int kt = 0; kt < Hz; kt += 16) {
        // Hs: flat contiguous copy of h_in[kt..kt+15][0..63]
        const float4* src = (const float4*)(h_in + (size_t)kt * 64);
        float4* dst = (float4*)&Hs[0][0];
        dst[tid * 2]     = src[tid * 2];
        dst[tid * 2 + 1] = src[tid * 2 + 1];
        *(float4*)&Ws[wk][wj] =
            *(const float4*)(Wh + (size_t)(kt + wk) * G4 + wg * Hz + c0 + wc);
        __syncthreads();

#pragma unroll
        for (int k = 0; k < 16; k++) {
            float4 a = *(float4*)&Hs[k][ty * 4];
            float4 b = *(float4*)&Ws[k][tx * 4];
            float aa[4] = {a.x, a.y, a.z, a.w};
            float bb[4] = {b.x, b.y, b.z, b.w};
#pragma unroll
            for (int i = 0; i < 4; i++)
#pragma unroll
                for (int j = 0; j < 4; j++) acc[i][j] += aa[i] * bb[j];
        }
        __syncthreads();
    }

    // gates -> smem (add xw)
#pragma unroll
    for (int i = 0; i < 4; i++) {
        int b = ty * 4 + i;
#pragma unroll
        for (int jj = 0; jj < 4; jj++) {
            int j = tx * 4 + jj;
            int n = (j >> 3) * Hz + c0 + (j & 7);
            Gs[b][j] = acc[i][jj] + xw_t[(size_t)b * G4 + n];
        }
    }
    __syncthreads();

    // pointwise LSTM update for the 8 owned h-cols x 64 rows
    for (int e = tid; e < 512; e += 128) {
        int b  = e & 63;
        int cc = e >> 6;                  // 0..7
        float ig = Gs[b][cc];
        float jg = Gs[b][8 + cc];
        float fg = Gs[b][16 + cc];
        float og = Gs[b][24 + cc];
        int ci = (c0 + cc) * 64 + b;
        float cold = g_c[ci];
        float cn = cold * sigm(fg + 1.0f) + sigm(ig) * tanhf(jg);
        float hn = tanhf(cn) * sigm(og);
        g_c[ci]  = cn;
        h_out[ci] = hn;
        if (t == seqlen[b] - 1) g_final[(size_t)b * Hz + c0 + cc] = hn;
    }
}

// ---------------- dense = relu(final @ dense_w + dense_b) ----------------
__global__ void dense_kernel(const float* __restrict__ dw, const float* __restrict__ db) {
    int b = blockIdx.x;
    int d = threadIdx.x;    // 512 threads
    const float* f = g_final + (size_t)b * Hz;
    float s0 = 0.f, s1 = 0.f, s2 = 0.f, s3 = 0.f;
#pragma unroll 4
    for (int k = 0; k < Hz; k += 4) {
        s0 += f[k]     * dw[(size_t)(k)     * Dz + d];
        s1 += f[k + 1] * dw[(size_t)(k + 1) * Dz + d];
        s2 += f[k + 2] * dw[(size_t)(k + 2) * Dz + d];
        s3 += f[k + 3] * dw[(size_t)(k + 3) * Dz + d];
    }
    float s = (s0 + s1) + (s2 + s3) + db[d];
    g_dense[(size_t)b * Dz + d] = fmaxf(s, 0.f);
}

// ---------------- logits = dense @ pred_w + pred_b ----------------
__global__ void logits_kernel(const float* __restrict__ pw, const float* __restrict__ pb,
                              float* __restrict__ out) {
    int tid = threadIdx.x;
    if (tid >= Bz * Cz) return;
    int b  = tid >> 1;
    int cc = tid & 1;
    const float* dn = g_dense + (size_t)b * Dz;
    float s = 0.f;
#pragma unroll 4
    for (int d = 0; d < Dz; d++) s += dn[d] * pw[(size_t)d * Cz + cc];
    out[b * Cz + cc] = s + pb[cc];
}

// ---------------- launch ----------------
extern "C" void kernel_launch(void* const* d_in, const int* in_sizes, int n_in,
                              void* d_out, int out_size) {
    const int*   X      = (const int*)d_in[0];
    const int*   seqlen = (const int*)d_in[1];
    const float* emb    = (const float*)d_in[2];
    const float* Wf     = (const float*)d_in[3];   // [1536, 4096]
    const float* bias   = (const float*)d_in[4];
    const float* dw     = (const float*)d_in[5];
    const float* db     = (const float*)d_in[6];
    const float* pw     = (const float*)d_in[7];
    const float* pb     = (const float*)d_in[8];
    float* out = (float*)d_out;

    init_kernel<<<128, 512>>>();
    xw_gemm<<<dim3(G4 / 128, (Sz * Bz) / 128), 256>>>(X, emb, Wf, bias);

    const float* Wh = Wf + (size_t)Ez * G4;        // recurrent weight rows
    for (int t = 0; t < Sz; t++) {
        step_kernel<<<Hz / 8, 128>>>(Wh, seqlen, t);
    }
    dense_kernel<<<Bz, Dz>>>(dw, db);
    logits_kernel<<<1, 128>>>(pw, pb, out);
}

// round 3
// speedup vs baseline: 1.7272x; 1.7272x over previous
#include <cuda_runtime.h>
#include <cuda_bf16.h>
#include <stdint.h>

#define Bz 64
#define Sz 256
#define Ez 512
#define Hz 1024
#define G4 4096   // 4*Hz
#define Dz 512
#define Cz 2

// ---------------- device scratch (no cudaMalloc allowed) ----------------
__device__ __align__(128) float g_xw2[(size_t)Sz * G4 * Bz];        // [s][n'][b]
__device__ __align__(128) __nv_bfloat16 g_wt_hi[(size_t)G4 * Hz];   // Wh^T [n'][k]
__device__ __align__(128) __nv_bfloat16 g_wt_lo[(size_t)G4 * Hz];
__device__ __align__(128) __nv_bfloat16 g_wx_hi[(size_t)G4 * Ez];   // Wx^T [n'][k]
__device__ __align__(128) __nv_bfloat16 g_wx_lo[(size_t)G4 * Ez];
__device__ __align__(128) __nv_bfloat16 g_a_hi[(size_t)Sz * Bz * Ez]; // gathered emb [m][k]
__device__ __align__(128) __nv_bfloat16 g_a_lo[(size_t)Sz * Bz * Ez];
__device__ __align__(128) __nv_bfloat16 g_h_hi[2][(size_t)Bz * Hz];  // h [b][k] ping-pong
__device__ __align__(128) __nv_bfloat16 g_h_lo[2][(size_t)Bz * Hz];
__device__ __align__(128) float g_bias2[G4];                         // permuted bias
__device__ __align__(128) float g_c[Hz * Bz];                        // cell [c][b]
__device__ __align__(128) float g_final[(size_t)Bz * Hz];            // [b][h]
__device__ __align__(128) float g_dense[Bz * Dz];

// ================= PTX helpers (non-'a' features only) =================
__device__ __forceinline__ uint32_t smem_u32(const void* p) {
    uint32_t a;
    asm("{ .reg .u64 t; cvta.to.shared.u64 t, %1; cvt.u32.u64 %0, t; }" : "=r"(a) : "l"(p));
    return a;
}
#define CP16(dst, src) \
    asm volatile("cp.async.cg.shared.global [%0], [%1], 16;" :: "r"((uint32_t)(dst)), "l"(src))
#define CP_COMMIT() asm volatile("cp.async.commit_group;" ::: "memory")
#define CP_WAIT0()  asm volatile("cp.async.wait_group 0;" ::: "memory")
#define CP_WAIT1()  asm volatile("cp.async.wait_group 1;" ::: "memory")

#define LDSM4(r, addr) \
    asm volatile("ldmatrix.sync.aligned.m8n8.x4.shared.b16 {%0,%1,%2,%3}, [%4];" \
        : "=r"((r)[0]), "=r"((r)[1]), "=r"((r)[2]), "=r"((r)[3]) : "r"(addr))
#define LDSM2(r, addr) \
    asm volatile("ldmatrix.sync.aligned.m8n8.x2.shared.b16 {%0,%1}, [%2];" \
        : "=r"((r)[0]), "=r"((r)[1]) : "r"(addr))
#define MMA(d, a, b) \
    asm volatile("mma.sync.aligned.m16n8k16.row.col.f32.bf16.bf16.f32 " \
        "{%0,%1,%2,%3},{%4,%5,%6,%7},{%8,%9},{%0,%1,%2,%3};" \
        : "+f"((d)[0]), "+f"((d)[1]), "+f"((d)[2]), "+f"((d)[3]) \
        : "r"((a)[0]), "r"((a)[1]), "r"((a)[2]), "r"((a)[3]), "r"((b)[0]), "r"((b)[1]))

__device__ __forceinline__ float sigm(float x) { return 1.f / (1.f + __expf(-x)); }
__device__ __forceinline__ float tanh_f(float x) { return 1.f - 2.f / (__expf(2.f * x) + 1.f); }

// smem tile geometry: 64 rows x 128 bf16, padded rows (272B) for conflict-free ldmatrix
#define ROWB 272
#define MATB (64 * ROWB)      // 17408
#define BUFB (4 * MATB)       // 69632 (Ah, Al, Bh, Bl)
#define SMEM_TOTAL (2 * BUFB) // 139264

// ---------------- init: zero h and c ----------------
__global__ void init_kernel() {
    int i = blockIdx.x * blockDim.x + threadIdx.x;
    if (i < Bz * Hz) {
        __nv_bfloat16 z = __float2bfloat16(0.f);
        g_h_hi[0][i] = z; g_h_hi[1][i] = z;
        g_h_lo[0][i] = z; g_h_lo[1][i] = z;
        g_c[i] = 0.f;
    }
}

// ---------------- prep: transpose+split W -> [n'=c*4+g][k] bf16 hi/lo ----------------
// sel==0: Wx (K=512) -> g_wx;  sel==1: Wh (K=1024) -> g_wt
__global__ __launch_bounds__(256) void prep_tr(const float* __restrict__ src, int K, int sel) {
    __shared__ float tile[32][33];
    int n0 = blockIdx.x * 32, k0 = blockIdx.y * 32;
    int tx = threadIdx.x & 31, ty = threadIdx.x >> 5;   // 32 x 8
#pragma unroll
    for (int r = 0; r < 4; r++)
        tile[ty + r * 8][tx] = src[(size_t)(k0 + ty + r * 8) * G4 + n0 + tx];
    __syncthreads();
    __nv_bfloat16* dh = sel ? g_wt_hi : g_wx_hi;
    __nv_bfloat16* dl = sel ? g_wt_lo : g_wx_lo;
#pragma unroll
    for (int r = 0; r < 4; r++) {
        int n = n0 + ty + r * 8;
        int np = (n & 1023) * 4 + (n >> 10);
        float v = tile[tx][ty + r * 8];
        __nv_bfloat16 hi = __float2bfloat16(v);
        dh[(size_t)np * K + k0 + tx] = hi;
        dl[(size_t)np * K + k0 + tx] = __float2bfloat16(v - __bfloat162float(hi));
    }
}

// ---------------- prep: gather emb rows, split to bf16 hi/lo [m][k] ----------------
__global__ void prep_emb(const int* __restrict__ X, const float* __restrict__ emb) {
    int m = blockIdx.x;                 // 0..16383, m = s*64+b
    int s = m >> 6, b = m & 63;
    int row = X[b * Sz + s];
    const float4* src = (const float4*)(emb + (size_t)row * Ez);
    int k4 = threadIdx.x;               // 128 threads, 4 elems each
    float4 v = src[k4];
    __nv_bfloat16 hx = __float2bfloat16(v.x), hy = __float2bfloat16(v.y);
    __nv_bfloat16 hz = __float2bfloat16(v.z), hw = __float2bfloat16(v.w);
    __nv_bfloat162* dh = (__nv_bfloat162*)(g_a_hi + (size_t)m * Ez);
    __nv_bfloat162* dl = (__nv_bfloat162*)(g_a_lo + (size_t)m * Ez);
    dh[k4 * 2]     = __nv_bfloat162(hx, hy);
    dh[k4 * 2 + 1] = __nv_bfloat162(hz, hw);
    dl[k4 * 2]     = __nv_bfloat162(__float2bfloat16(v.x - __bfloat162float(hx)),
                                    __float2bfloat16(v.y - __bfloat162float(hy)));
    dl[k4 * 2 + 1] = __nv_bfloat162(__float2bfloat16(v.z - __bfloat162float(hz)),
                                    __float2bfloat16(v.w - __bfloat162float(hw)));
}

__global__ void prep_bias(const float* __restrict__ bias) {
    int n = blockIdx.x * blockDim.x + threadIdx.x;
    if (n < G4) g_bias2[(n & 1023) * 4 + (n >> 10)] = bias[n];
}

// ---------------- shared GEMM building blocks ----------------
__device__ __forceinline__ void load_mat(uint32_t dst, const __nv_bfloat16* src,
                                         int stride_elems, int tid) {
#pragma unroll
    for (int i = 0; i < 8; i++) {
        int idx = i * 128 + tid;
        int row = idx >> 4, seg = idx & 15;
        CP16(dst + row * ROWB + seg * 16,
             (const char*)(src + (size_t)row * stride_elems) + seg * 16);
    }
}

// compute one 128-k chunk: warp tile 32x32 at (mbase, nbase); acc[2][4][4]
__device__ __forceinline__ void compute_chunk(uint32_t buf, int lane, int mbase, int nbase,
                                              float acc[2][4][4]) {
    const uint32_t aH = buf, aL = buf + MATB, bH = buf + 2 * MATB, bL = buf + 3 * MATB;
    const int g = lane >> 3;
    const int arow = (lane & 7) + ((g & 1) << 3);
    const int ahalf = (g >> 1) * 16;
    const int brow = lane & 7;
    const int bhalf = ((lane >> 3) & 1) * 16;
#pragma unroll
    for (int k16 = 0; k16 < 8; k16++) {
        const uint32_t kb = k16 * 32;
        uint32_t ah[2][4], al[2][4], bh[4][2], bl[4][2];
#pragma unroll
        for (int mt = 0; mt < 2; mt++) {
            uint32_t ao = (uint32_t)((mbase + mt * 16 + arow) * ROWB) + kb + ahalf;
            LDSM4(ah[mt], aH + ao);
            LDSM4(al[mt], aL + ao);
        }
#pragma unroll
        for (int nt = 0; nt < 4; nt++) {
            uint32_t bo = (uint32_t)((nbase + nt * 8 + brow) * ROWB) + kb + bhalf;
            LDSM2(bh[nt], bH + bo);
            LDSM2(bl[nt], bL + bo);
        }
#pragma unroll
        for (int mt = 0; mt < 2; mt++)
#pragma unroll
            for (int nt = 0; nt < 4; nt++) {
                MMA(acc[mt][nt], ah[mt], bh[nt]);
                MMA(acc[mt][nt], ah[mt], bl[nt]);
                MMA(acc[mt][nt], al[mt], bh[nt]);
            }
    }
}

__device__ __forceinline__ void store_frags_to_Gs(float* Gs, int lane, int mbase, int nbase,
                                                  float acc[2][4][4]) {
    const int r = lane >> 2, c2 = (lane & 3) * 2;
#pragma unroll
    for (int mt = 0; mt < 2; mt++)
#pragma unroll
        for (int nt = 0; nt < 4; nt++) {
            int m = mbase + mt * 16 + r;
            int n = nbase + nt * 8 + c2;
            Gs[n * 68 + m]           = acc[mt][nt][0];
            Gs[(n + 1) * 68 + m]     = acc[mt][nt][1];
            Gs[n * 68 + m + 8]       = acc[mt][nt][2];
            Gs[(n + 1) * 68 + m + 8] = acc[mt][nt][3];
        }
}

// ---------------- xw GEMM: g_xw2[s][n'][b] = emb_m @ Wx^T + bias (bf16x3) ----------------
__global__ __launch_bounds__(128, 1) void xw_mma() {
    extern __shared__ char smem[];
    const uint32_t sb = smem_u32(smem);
    const int tid = threadIdx.x, lane = tid & 31, w = tid >> 5;
    const int np0 = blockIdx.x * 64;
    const int s = blockIdx.y;
    const __nv_bfloat16* Ah = g_a_hi + (size_t)s * Bz * Ez;
    const __nv_bfloat16* Al = g_a_lo + (size_t)s * Bz * Ez;
    const __nv_bfloat16* Bh = g_wx_hi + (size_t)np0 * Ez;
    const __nv_bfloat16* Bl = g_wx_lo + (size_t)np0 * Ez;

    float acc[2][4][4] = {};
    const int mbase = (w & 1) * 32, nbase = (w >> 1) * 32;

    load_mat(sb, Ah, Ez, tid);
    load_mat(sb + MATB, Al, Ez, tid);
    load_mat(sb + 2 * MATB, Bh, Ez, tid);
    load_mat(sb + 3 * MATB, Bl, Ez, tid);
    CP_COMMIT();

    for (int c = 0; c < 4; c++) {
        if (c < 3) {
            int kc = (c + 1) * 128;
            uint32_t buf = sb + ((c + 1) & 1) * BUFB;
            load_mat(buf, Ah + kc, Ez, tid);
            load_mat(buf + MATB, Al + kc, Ez, tid);
            load_mat(buf + 2 * MATB, Bh + kc, Ez, tid);
            load_mat(buf + 3 * MATB, Bl + kc, Ez, tid);
            CP_COMMIT();
            CP_WAIT1();
        } else {
            CP_WAIT0();
        }
        __syncthreads();
        compute_chunk(sb + (c & 1) * BUFB, lane, mbase, nbase, acc);
        __syncthreads();
    }

    float* Gs = (float*)smem;   // [64][68]
    store_frags_to_Gs(Gs, lane, mbase, nbase, acc);
    __syncthreads();

    float* outb = g_xw2 + ((size_t)s * G4 + np0) * Bz;
#pragma unroll
    for (int i = 0; i < 32; i++) {
        int e = i * 128 + tid;               // e = n'local*64 + b
        int nl = e >> 6, b = e & 63;
        outb[e] = Gs[nl * 68 + b] + g_bias2[np0 + nl];
    }
}

// ---------------- LSTM step: gates = h @ Wh^T (bf16x3 HMMA) + fused pointwise ----------------
__global__ __launch_bounds__(128, 1) void step_mma(const int* __restrict__ seqlen, int t) {
    extern __shared__ char smem[];
    const uint32_t sb = smem_u32(smem);
    const int tid = threadIdx.x, lane = tid & 31, w = tid >> 5;
    const int blk = blockIdx.x;
    const int np0 = blk * 64, c0 = blk * 16;
    const __nv_bfloat16* h_hi = g_h_hi[t & 1];
    const __nv_bfloat16* h_lo = g_h_lo[t & 1];
    __nv_bfloat16* o_hi = g_h_hi[(t + 1) & 1];
    __nv_bfloat16* o_lo = g_h_lo[(t + 1) & 1];
    const __nv_bfloat16* Bh = g_wt_hi + (size_t)np0 * Hz;
    const __nv_bfloat16* Bl = g_wt_lo + (size_t)np0 * Hz;

    float acc[2][4][4] = {};
    const int mbase = (w & 1) * 32, nbase = (w >> 1) * 32;

    load_mat(sb, h_hi, Hz, tid);
    load_mat(sb + MATB, h_lo, Hz, tid);
    load_mat(sb + 2 * MATB, Bh, Hz, tid);
    load_mat(sb + 3 * MATB, Bl, Hz, tid);
    CP_COMMIT();

    for (int c = 0; c < 8; c++) {
        if (c < 7) {
            int kc = (c + 1) * 128;
            uint32_t buf = sb + ((c + 1) & 1) * BUFB;
            load_mat(buf, h_hi + kc, Hz, tid);
            load_mat(buf + MATB, h_lo + kc, Hz, tid);
            load_mat(buf + 2 * MATB, Bh + kc, Hz, tid);
            load_mat(buf + 3 * MATB, Bl + kc, Hz, tid);
            CP_COMMIT();
            CP_WAIT1();
        } else {
            CP_WAIT0();
        }
        __syncthreads();
        compute_chunk(sb + (c & 1) * BUFB, lane, mbase, nbase, acc);
        __syncthreads();
    }

    float* Gs = (float*)smem;   // [64 n'][68] (reuses buffer 0 region)
    store_frags_to_Gs(Gs, lane, mbase, nbase, acc);
    __syncthreads();

    const float* xwb = g_xw2 + ((size_t)t * G4 + np0) * Bz;
#pragma unroll
    for (int i = 0; i < 8; i++) {
        int e = i * 128 + tid;               // 16 cols x 64 batch
        int col = e >> 6, b = e & 63;
        float ig = Gs[(col * 4 + 0) * 68 + b] + xwb[(col * 4 + 0) * Bz + b];
        float jg = Gs[(col * 4 + 1) * 68 + b] + xwb[(col * 4 + 1) * Bz + b];
        float fg = Gs[(col * 4 + 2) * 68 + b] + xwb[(col * 4 + 2) * Bz + b];
        float og = Gs[(col * 4 + 3) * 68 + b] + xwb[(col * 4 + 3) * Bz + b];
        int ci = (c0 + col) * Bz + b;
        float cn = g_c[ci] * sigm(fg + 1.0f) + sigm(ig) * tanh_f(jg);
        float hn = tanh_f(cn) * sigm(og);
        g_c[ci] = cn;
        __nv_bfloat16 hi = __float2bfloat16(hn);
        o_hi[(size_t)b * Hz + c0 + col] = hi;
        o_lo[(size_t)b * Hz + c0 + col] = __float2bfloat16(hn - __bfloat162float(hi));
        if (t == __ldg(seqlen + b) - 1) g_final[(size_t)b * Hz + c0 + col] = hn;
    }
}

// ---------------- dense = relu(final @ dense_w + dense_b) ----------------
__global__ void dense_kernel(const float* __restrict__ dw, const float* __restrict__ db) {
    int b = blockIdx.x;
    int d = threadIdx.x;    // 512 threads
    const float* f = g_final + (size_t)b * Hz;
    float s0 = 0.f, s1 = 0.f, s2 = 0.f, s3 = 0.f;
#pragma unroll 4
    for (int k = 0; k < Hz; k += 4) {
        s0 += f[k]     * dw[(size_t)(k)     * Dz + d];
        s1 += f[k + 1] * dw[(size_t)(k + 1) * Dz + d];
        s2 += f[k + 2] * dw[(size_t)(k + 2) * Dz + d];
        s3 += f[k + 3] * dw[(size_t)(k + 3) * Dz + d];
    }
    float s = (s0 + s1) + (s2 + s3) + db[d];
    g_dense[(size_t)b * Dz + d] = fmaxf(s, 0.f);
}

// ---------------- logits = dense @ pred_w + pred_b ----------------
__global__ void logits_kernel(const float* __restrict__ pw, const float* __restrict__ pb,
                              float* __restrict__ out) {
    int tid = threadIdx.x;
    if (tid >= Bz * Cz) return;
    int b = tid >> 1;
    int cc = tid & 1;
    const float* dn = g_dense + (size_t)b * Dz;
    float s = 0.f;
#pragma unroll 4
    for (int d = 0; d < Dz; d++) s += dn[d] * pw[(size_t)d * Cz + cc];
    out[b * Cz + cc] = s + pb[cc];
}

// ---------------- launch ----------------
extern "C" void kernel_launch(void* const* d_in, const int* in_sizes, int n_in,
                              void* d_out, int out_size) {
    const int*   X      = (const int*)d_in[0];
    const int*   seqlen = (const int*)d_in[1];
    const float* emb    = (const float*)d_in[2];
    const float* Wf     = (const float*)d_in[3];   // [1536, 4096]
    const float* bias   = (const float*)d_in[4];
    const float* dw     = (const float*)d_in[5];
    const float* db     = (const float*)d_in[6];
    const float* pw     = (const float*)d_in[7];
    const float* pb     = (const float*)d_in[8];
    float* out = (float*)d_out;

    cudaFuncSetAttribute(step_mma, cudaFuncAttributeMaxDynamicSharedMemorySize, SMEM_TOTAL);
    cudaFuncSetAttribute(xw_mma, cudaFuncAttributeMaxDynamicSharedMemorySize, SMEM_TOTAL);

    init_kernel<<<(Bz * Hz + 255) / 256, 256>>>();
    prep_tr<<<dim3(G4 / 32, Ez / 32), 256>>>(Wf, Ez, 0);                 // Wx
    prep_tr<<<dim3(G4 / 32, Hz / 32), 256>>>(Wf + (size_t)Ez * G4, Hz, 1); // Wh
    prep_emb<<<Sz * Bz, 128>>>(X, emb);
    prep_bias<<<G4 / 256, 256>>>(bias);

    xw_mma<<<dim3(G4 / 64, Sz), 128, SMEM_TOTAL>>>();

    for (int t = 0; t < Sz; t++) {
        step_mma<<<64, 128, SMEM_TOTAL>>>(seqlen, t);
    }
    dense_kernel<<<Bz, Dz>>>(dw, db);
    logits_kernel<<<1, 128>>>(pw, pb, out);
}

// round 4
// speedup vs baseline: 1.8078x; 1.0467x over previous
#include <cuda_runtime.h>
#include <cuda_bf16.h>
#include <stdint.h>

#define Bz 64
#define Sz 256
#define Ez 512
#define Hz 1024
#define G4 4096   // 4*Hz
#define Dz 512
#define Cz 2

// ---------------- device scratch (no cudaMalloc allowed) ----------------
__device__ __align__(128) float g_xw2[(size_t)Sz * G4 * Bz];        // [s][n'][b]
__device__ __align__(128) __nv_bfloat16 g_wt_hi[(size_t)G4 * Hz];   // Wh^T [n'][k]
__device__ __align__(128) __nv_bfloat16 g_wt_lo[(size_t)G4 * Hz];
__device__ __align__(128) __nv_bfloat16 g_wx_hi[(size_t)G4 * Ez];   // Wx^T [n'][k]
__device__ __align__(128) __nv_bfloat16 g_wx_lo[(size_t)G4 * Ez];
__device__ __align__(128) __nv_bfloat16 g_a_hi[(size_t)Sz * Bz * Ez]; // gathered emb [m][k]
__device__ __align__(128) __nv_bfloat16 g_a_lo[(size_t)Sz * Bz * Ez];
__device__ __align__(128) __nv_bfloat16 g_h_hi[2][(size_t)Bz * Hz];  // h [b][k] ping-pong
__device__ __align__(128) __nv_bfloat16 g_h_lo[2][(size_t)Bz * Hz];
__device__ __align__(128) float g_bias2[G4];                         // permuted bias
__device__ __align__(128) float g_c[Hz * Bz];                        // cell [c][b]
__device__ __align__(128) float g_final[(size_t)Bz * Hz];            // [b][h]
__device__ __align__(128) float g_dense[Bz * Dz];
__device__ int g_cnt;                                                // barrier counter
__device__ int g_flag;                                               // barrier release flag

// ================= PTX helpers (non-'a' features only) =================
__device__ __forceinline__ uint32_t smem_u32(const void* p) {
    uint32_t a;
    asm("{ .reg .u64 t; cvta.to.shared.u64 t, %1; cvt.u32.u64 %0, t; }" : "=r"(a) : "l"(p));
    return a;
}
#define CP16(dst, src) \
    asm volatile("cp.async.cg.shared.global [%0], [%1], 16;" :: "r"((uint32_t)(dst)), "l"(src))
#define CP_COMMIT() asm volatile("cp.async.commit_group;" ::: "memory")
#define CP_WAITN(n) asm volatile("cp.async.wait_group %0;" :: "n"(n) : "memory")

#define LDSM4(r, addr) \
    asm volatile("ldmatrix.sync.aligned.m8n8.x4.shared.b16 {%0,%1,%2,%3}, [%4];" \
        : "=r"((r)[0]), "=r"((r)[1]), "=r"((r)[2]), "=r"((r)[3]) : "r"(addr))
#define LDSM2(r, addr) \
    asm volatile("ldmatrix.sync.aligned.m8n8.x2.shared.b16 {%0,%1}, [%2];" \
        : "=r"((r)[0]), "=r"((r)[1]) : "r"(addr))
#define MMA(d, a, b) \
    asm volatile("mma.sync.aligned.m16n8k16.row.col.f32.bf16.bf16.f32 " \
        "{%0,%1,%2,%3},{%4,%5,%6,%7},{%8,%9},{%0,%1,%2,%3};" \
        : "+f"((d)[0]), "+f"((d)[1]), "+f"((d)[2]), "+f"((d)[3]) \
        : "r"((a)[0]), "r"((a)[1]), "r"((a)[2]), "r"((a)[3]), "r"((b)[0]), "r"((b)[1]))

__device__ __forceinline__ float sigm(float x) { return 1.f / (1.f + __expf(-x)); }
__device__ __forceinline__ float tanh_f(float x) { return 1.f - 2.f / (__expf(2.f * x) + 1.f); }

// smem tile geometry: 64 rows x 128 bf16, padded rows (272B) for conflict-free ldmatrix
#define ROWB 272
#define MATB (64 * ROWB)      // 17408
#define BUFB (4 * MATB)       // 69632 (Ah, Al, Bh, Bl)
#define SMEM_XW (2 * BUFB)    // 139264 (xw kernel: 2-stage)
#define SMEM_ST (3 * BUFB)    // 208896 (persistent step kernel: 3-stage)

// ---------------- init: zero h and c, reset barrier ----------------
__global__ void init_kernel() {
    int i = blockIdx.x * blockDim.x + threadIdx.x;
    if (i == 0) { g_cnt = 0; g_flag = 0; }
    if (i < Bz * Hz) {
        __nv_bfloat16 z = __float2bfloat16(0.f);
        g_h_hi[0][i] = z; g_h_hi[1][i] = z;
        g_h_lo[0][i] = z; g_h_lo[1][i] = z;
        g_c[i] = 0.f;
    }
}

// ---------------- prep: transpose+split W -> [n'=c*4+g][k] bf16 hi/lo ----------------
__global__ __launch_bounds__(256) void prep_tr(const float* __restrict__ src, int K, int sel) {
    __shared__ float tile[32][33];
    int n0 = blockIdx.x * 32, k0 = blockIdx.y * 32;
    int tx = threadIdx.x & 31, ty = threadIdx.x >> 5;   // 32 x 8
#pragma unroll
    for (int r = 0; r < 4; r++)
        tile[ty + r * 8][tx] = src[(size_t)(k0 + ty + r * 8) * G4 + n0 + tx];
    __syncthreads();
    __nv_bfloat16* dh = sel ? g_wt_hi : g_wx_hi;
    __nv_bfloat16* dl = sel ? g_wt_lo : g_wx_lo;
#pragma unroll
    for (int r = 0; r < 4; r++) {
        int n = n0 + ty + r * 8;
        int np = (n & 1023) * 4 + (n >> 10);
        float v = tile[tx][ty + r * 8];
        __nv_bfloat16 hi = __float2bfloat16(v);
        dh[(size_t)np * K + k0 + tx] = hi;
        dl[(size_t)np * K + k0 + tx] = __float2bfloat16(v - __bfloat162float(hi));
    }
}

// ---------------- prep: gather emb rows, split to bf16 hi/lo [m][k] ----------------
__global__ void prep_emb(const int* __restrict__ X, const float* __restrict__ emb) {
    int m = blockIdx.x;                 // m = s*64+b
    int s = m >> 6, b = m & 63;
    int row = X[b * Sz + s];
    const float4* src = (const float4*)(emb + (size_t)row * Ez);
    int k4 = threadIdx.x;
    float4 v = src[k4];
    __nv_bfloat16 hx = __float2bfloat16(v.x), hy = __float2bfloat16(v.y);
    __nv_bfloat16 hz = __float2bfloat16(v.z), hw = __float2bfloat16(v.w);
    __nv_bfloat162* dh = (__nv_bfloat162*)(g_a_hi + (size_t)m * Ez);
    __nv_bfloat162* dl = (__nv_bfloat162*)(g_a_lo + (size_t)m * Ez);
    dh[k4 * 2]     = __nv_bfloat162(hx, hy);
    dh[k4 * 2 + 1] = __nv_bfloat162(hz, hw);
    dl[k4 * 2]     = __nv_bfloat162(__float2bfloat16(v.x - __bfloat162float(hx)),
                                    __float2bfloat16(v.y - __bfloat162float(hy)));
    dl[k4 * 2 + 1] = __nv_bfloat162(__float2bfloat16(v.z - __bfloat162float(hz)),
                                    __float2bfloat16(v.w - __bfloat162float(hw)));
}

__global__ void prep_bias(const float* __restrict__ bias) {
    int n = blockIdx.x * blockDim.x + threadIdx.x;
    if (n < G4) g_bias2[(n & 1023) * 4 + (n >> 10)] = bias[n];
}

// ---------------- shared GEMM building blocks ----------------
__device__ __forceinline__ void load_mat(uint32_t dst, const __nv_bfloat16* src,
                                         int stride_elems, int tid) {
#pragma unroll
    for (int i = 0; i < 8; i++) {
        int idx = i * 128 + tid;
        int row = idx >> 4, seg = idx & 15;
        CP16(dst + row * ROWB + seg * 16,
             (const char*)(src + (size_t)row * stride_elems) + seg * 16);
    }
}

__device__ __forceinline__ void compute_chunk(uint32_t buf, int lane, int mbase, int nbase,
                                              float acc[2][4][4]) {
    const uint32_t aH = buf, aL = buf + MATB, bH = buf + 2 * MATB, bL = buf + 3 * MATB;
    const int g = lane >> 3;
    const int arow = (lane & 7) + ((g & 1) << 3);
    const int ahalf = (g >> 1) * 16;
    const int brow = lane & 7;
    const int bhalf = ((lane >> 3) & 1) * 16;
#pragma unroll
    for (int k16 = 0; k16 < 8; k16++) {
        const uint32_t kb = k16 * 32;
        uint32_t ah[2][4], al[2][4], bh[4][2], bl[4][2];
#pragma unroll
        for (int mt = 0; mt < 2; mt++) {
            uint32_t ao = (uint32_t)((mbase + mt * 16 + arow) * ROWB) + kb + ahalf;
            LDSM4(ah[mt], aH + ao);
            LDSM4(al[mt], aL + ao);
        }
#pragma unroll
        for (int nt = 0; nt < 4; nt++) {
            uint32_t bo = (uint32_t)((nbase + nt * 8 + brow) * ROWB) + kb + bhalf;
            LDSM2(bh[nt], bH + bo);
            LDSM2(bl[nt], bL + bo);
        }
#pragma unroll
        for (int mt = 0; mt < 2; mt++)
#pragma unroll
            for (int nt = 0; nt < 4; nt++) {
                MMA(acc[mt][nt], ah[mt], bh[nt]);
                MMA(acc[mt][nt], ah[mt], bl[nt]);
                MMA(acc[mt][nt], al[mt], bh[nt]);
            }
    }
}

__device__ __forceinline__ void store_frags_to_Gs(float* Gs, int lane, int mbase, int nbase,
                                                  float acc[2][4][4]) {
    const int r = lane >> 2, c2 = (lane & 3) * 2;
#pragma unroll
    for (int mt = 0; mt < 2; mt++)
#pragma unroll
        for (int nt = 0; nt < 4; nt++) {
            int m = mbase + mt * 16 + r;
            int n = nbase + nt * 8 + c2;
            Gs[n * 68 + m]           = acc[mt][nt][0];
            Gs[(n + 1) * 68 + m]     = acc[mt][nt][1];
            Gs[n * 68 + m + 8]       = acc[mt][nt][2];
            Gs[(n + 1) * 68 + m + 8] = acc[mt][nt][3];
        }
}

// ---------------- xw GEMM: g_xw2[s][n'][b] = emb_m @ Wx^T + bias (bf16x3) ----------------
__global__ __launch_bounds__(128, 1) void xw_mma() {
    extern __shared__ char smem[];
    const uint32_t sb = smem_u32(smem);
    const int tid = threadIdx.x, lane = tid & 31, w = tid >> 5;
    const int np0 = blockIdx.x * 64;
    const int s = blockIdx.y;
    const __nv_bfloat16* Ah = g_a_hi + (size_t)s * Bz * Ez;
    const __nv_bfloat16* Al = g_a_lo + (size_t)s * Bz * Ez;
    const __nv_bfloat16* Bh = g_wx_hi + (size_t)np0 * Ez;
    const __nv_bfloat16* Bl = g_wx_lo + (size_t)np0 * Ez;

    float acc[2][4][4] = {};
    const int mbase = (w & 1) * 32, nbase = (w >> 1) * 32;

    load_mat(sb, Ah, Ez, tid);
    load_mat(sb + MATB, Al, Ez, tid);
    load_mat(sb + 2 * MATB, Bh, Ez, tid);
    load_mat(sb + 3 * MATB, Bl, Ez, tid);
    CP_COMMIT();

    for (int c = 0; c < 4; c++) {
        if (c < 3) {
            int kc = (c + 1) * 128;
            uint32_t buf = sb + ((c + 1) & 1) * BUFB;
            load_mat(buf, Ah + kc, Ez, tid);
            load_mat(buf + MATB, Al + kc, Ez, tid);
            load_mat(buf + 2 * MATB, Bh + kc, Ez, tid);
            load_mat(buf + 3 * MATB, Bl + kc, Ez, tid);
            CP_COMMIT();
            CP_WAITN(1);
        } else {
            CP_WAITN(0);
        }
        __syncthreads();
        compute_chunk(sb + (c & 1) * BUFB, lane, mbase, nbase, acc);
        __syncthreads();
    }

    float* Gs = (float*)smem;   // [64][68]
    store_frags_to_Gs(Gs, lane, mbase, nbase, acc);
    __syncthreads();

    float* outb = g_xw2 + ((size_t)s * G4 + np0) * Bz;
#pragma unroll
    for (int i = 0; i < 32; i++) {
        int e = i * 128 + tid;               // e = n'local*64 + b
        int nl = e >> 6, b = e & 63;
        outb[e] = Gs[nl * 68 + b] + g_bias2[np0 + nl];
    }
}

// ---------------- persistent LSTM recurrence ----------------
// 64 co-resident CTAs, one global barrier per step, 3-stage cp.async pipeline.
__device__ __forceinline__ void gbar_arrive_wait(int target, int tid) {
    __syncthreads();
    if (tid == 0) {
        int old;
        asm volatile("atom.add.release.gpu.global.s32 %0, [%1], 1;"
                     : "=r"(old) : "l"(&g_cnt) : "memory");
        if (old == 63) {
            g_cnt = 0;
            asm volatile("st.release.gpu.global.s32 [%0], %1;"
                         :: "l"(&g_flag), "r"(target) : "memory");
        } else {
            int f;
            do {
                asm volatile("ld.acquire.gpu.global.s32 %0, [%1];"
                             : "=r"(f) : "l"(&g_flag));
            } while (f < target);
        }
    }
    __syncthreads();
}

__global__ __launch_bounds__(128, 1) void steps_persistent(const int* __restrict__ seqlen) {
    extern __shared__ char smem[];
    const uint32_t sb = smem_u32(smem);
    const int tid = threadIdx.x, lane = tid & 31, w = tid >> 5;
    const int blk = blockIdx.x;
    const int np0 = blk * 64, c0 = blk * 16;
    const __nv_bfloat16* Bh = g_wt_hi + (size_t)np0 * Hz;
    const __nv_bfloat16* Bl = g_wt_lo + (size_t)np0 * Hz;
    const int mbase = (w & 1) * 32, nbase = (w >> 1) * 32;
    const int sl_b0 = __ldg(seqlen + (tid & 63));  // seq_len for batch row (tid&63)

    for (int t = 0; t < Sz; t++) {
        const __nv_bfloat16* h_hi = g_h_hi[t & 1];
        const __nv_bfloat16* h_lo = g_h_lo[t & 1];
        __nv_bfloat16* o_hi = g_h_hi[(t + 1) & 1];
        __nv_bfloat16* o_lo = g_h_lo[(t + 1) & 1];

        // W prefetch for chunks 0,1 — independent of h, overlaps the barrier
        load_mat(sb + 2 * MATB, Bh, Hz, tid);
        load_mat(sb + 3 * MATB, Bl, Hz, tid);
        CP_COMMIT();                               // group: W0
        load_mat(sb + BUFB + 2 * MATB, Bh + 128, Hz, tid);
        load_mat(sb + BUFB + 3 * MATB, Bl + 128, Hz, tid);
        CP_COMMIT();                               // group: W1

        if (t > 0) gbar_arrive_wait(t, tid);       // all CTAs finished step t-1

        load_mat(sb, h_hi, Hz, tid);
        load_mat(sb + MATB, h_lo, Hz, tid);
        CP_COMMIT();                               // group: H0
        load_mat(sb + BUFB, h_hi + 128, Hz, tid);
        load_mat(sb + BUFB + MATB, h_lo + 128, Hz, tid);
        CP_COMMIT();                               // group: H1

        float acc[2][4][4] = {};
#pragma unroll
        for (int c = 0; c < 8; c++) {
            if (c < 6) {
                int kc = (c + 2) * 128;
                uint32_t buf = sb + (uint32_t)((c + 2) % 3) * BUFB;
                load_mat(buf, h_hi + kc, Hz, tid);
                load_mat(buf + MATB, h_lo + kc, Hz, tid);
                load_mat(buf + 2 * MATB, Bh + kc, Hz, tid);
                load_mat(buf + 3 * MATB, Bl + kc, Hz, tid);
                CP_COMMIT();
                CP_WAITN(2);
            } else if (c == 6) {
                CP_WAITN(1);
            } else {
                CP_WAITN(0);
            }
            __syncthreads();
            compute_chunk(sb + (uint32_t)(c % 3) * BUFB, lane, mbase, nbase, acc);
            __syncthreads();
        }

        // gates staged in buffer 2 (not reused until after next barrier)
        float* Gs = (float*)(smem + 2 * BUFB);     // [64 n'][68]
        store_frags_to_Gs(Gs, lane, mbase, nbase, acc);
        __syncthreads();

        const float* xwb = g_xw2 + ((size_t)t * G4 + np0) * Bz;
        const bool is_last = (t == sl_b0 - 1);
#pragma unroll
        for (int i = 0; i < 8; i++) {
            int e = i * 128 + tid;                 // 16 cols x 64 batch
            int col = e >> 6, b = e & 63;
            float ig = Gs[(col * 4 + 0) * 68 + b] + xwb[(col * 4 + 0) * Bz + b];
            float jg = Gs[(col * 4 + 1) * 68 + b] + xwb[(col * 4 + 1) * Bz + b];
            float fg = Gs[(col * 4 + 2) * 68 + b] + xwb[(col * 4 + 2) * Bz + b];
            float og = Gs[(col * 4 + 3) * 68 + b] + xwb[(col * 4 + 3) * Bz + b];
            int ci = (c0 + col) * Bz + b;
            float cn = g_c[ci] * sigm(fg + 1.0f) + sigm(ig) * tanh_f(jg);
            float hn = tanh_f(cn) * sigm(og);
            g_c[ci] = cn;
            __nv_bfloat16 hi = __float2bfloat16(hn);
            o_hi[(size_t)b * Hz + c0 + col] = hi;
            o_lo[(size_t)b * Hz + c0 + col] = __float2bfloat16(hn - __bfloat162float(hi));
            if (is_last) g_final[(size_t)b * Hz + c0 + col] = hn;
        }
    }
}

// ---------------- dense = relu(final @ dense_w + dense_b) ----------------
__global__ void dense_kernel(const float* __restrict__ dw, const float* __restrict__ db) {
    int b = blockIdx.x;
    int d = threadIdx.x;    // 512 threads
    const float* f = g_final + (size_t)b * Hz;
    float s0 = 0.f, s1 = 0.f, s2 = 0.f, s3 = 0.f;
#pragma unroll 4
    for (int k = 0; k < Hz; k += 4) {
        s0 += f[k]     * dw[(size_t)(k)     * Dz + d];
        s1 += f[k + 1] * dw[(size_t)(k + 1) * Dz + d];
        s2 += f[k + 2] * dw[(size_t)(k + 2) * Dz + d];
        s3 += f[k + 3] * dw[(size_t)(k + 3) * Dz + d];
    }
    float s = (s0 + s1) + (s2 + s3) + db[d];
    g_dense[(size_t)b * Dz + d] = fmaxf(s, 0.f);
}

// ---------------- logits = dense @ pred_w + pred_b ----------------
__global__ void logits_kernel(const float* __restrict__ pw, const float* __restrict__ pb,
                              float* __restrict__ out) {
    int tid = threadIdx.x;
    if (tid >= Bz * Cz) return;
    int b = tid >> 1;
    int cc = tid & 1;
    const float* dn = g_dense + (size_t)b * Dz;
    float s = 0.f;
#pragma unroll 4
    for (int d = 0; d < Dz; d++) s += dn[d] * pw[(size_t)d * Cz + cc];
    out[b * Cz + cc] = s + pb[cc];
}

// ---------------- launch ----------------
extern "C" void kernel_launch(void* const* d_in, const int* in_sizes, int n_in,
                              void* d_out, int out_size) {
    const int*   X      = (const int*)d_in[0];
    const int*   seqlen = (const int*)d_in[1];
    const float* emb    = (const float*)d_in[2];
    const float* Wf     = (const float*)d_in[3];   // [1536, 4096]
    const float* bias   = (const float*)d_in[4];
    const float* dw     = (const float*)d_in[5];
    const float* db     = (const float*)d_in[6];
    const float* pw     = (const float*)d_in[7];
    const float* pb     = (const float*)d_in[8];
    float* out = (float*)d_out;

    cudaFuncSetAttribute(xw_mma, cudaFuncAttributeMaxDynamicSharedMemorySize, SMEM_XW);
    cudaFuncSetAttribute(steps_persistent, cudaFuncAttributeMaxDynamicSharedMemorySize, SMEM_ST);

    init_kernel<<<(Bz * Hz + 255) / 256, 256>>>();
    prep_tr<<<dim3(G4 / 32, Ez / 32), 256>>>(Wf, Ez, 0);                   // Wx
    prep_tr<<<dim3(G4 / 32, Hz / 32), 256>>>(Wf + (size_t)Ez * G4, Hz, 1); // Wh
    prep_emb<<<Sz * Bz, 128>>>(X, emb);
    prep_bias<<<G4 / 256, 256>>>(bias);

    xw_mma<<<dim3(G4 / 64, Sz), 128, SMEM_XW>>>();

    steps_persistent<<<64, 128, SMEM_ST>>>(seqlen);

    dense_kernel<<<Bz, Dz>>>(dw, db);
    logits_kernel<<<1, 128>>>(pw, pb, out);
}

// round 5
// speedup vs baseline: 3.0703x; 1.6984x over previous
#include <cuda_runtime.h>
#include <cuda_bf16.h>
#include <stdint.h>

#define Bz 64
#define Sz 256
#define Ez 512
#define Hz 1024
#define G4 4096   // 4*Hz
#define Dz 512
#define Cz 2

// ---------------- device scratch (no cudaMalloc allowed) ----------------
__device__ __align__(128) float g_xw2[(size_t)Sz * G4 * Bz];        // [s][n'][b]
__device__ __align__(128) __nv_bfloat16 g_wt_hi[(size_t)G4 * Hz];   // Wh^T [n'][k]
__device__ __align__(128) __nv_bfloat16 g_wt_lo[(size_t)G4 * Hz];
__device__ __align__(128) __nv_bfloat16 g_wx_hi[(size_t)G4 * Ez];   // Wx^T [n'][k]
__device__ __align__(128) __nv_bfloat16 g_wx_lo[(size_t)G4 * Ez];
__device__ __align__(128) __nv_bfloat16 g_a_hi[(size_t)Sz * Bz * Ez]; // gathered emb [m][k]
__device__ __align__(128) __nv_bfloat16 g_a_lo[(size_t)Sz * Bz * Ez];
__device__ __align__(128) __nv_bfloat16 g_h_hi[2][(size_t)Bz * Hz];  // h [b][k] ping-pong
__device__ __align__(128) __nv_bfloat16 g_h_lo[2][(size_t)Bz * Hz];
__device__ __align__(128) float g_bias2[G4];                         // permuted bias
__device__ __align__(128) float g_c[Hz * Bz];                        // cell [c][b]
__device__ __align__(128) float g_final[(size_t)Bz * Hz];            // [b][h]
__device__ __align__(128) float g_dense[Bz * Dz];
__device__ int g_cnt;                                                // barrier counter
__device__ int g_flag;                                               // barrier release flag

// ================= PTX helpers (non-'a' features only) =================
__device__ __forceinline__ uint32_t smem_u32(const void* p) {
    uint32_t a;
    asm("{ .reg .u64 t; cvta.to.shared.u64 t, %1; cvt.u32.u64 %0, t; }" : "=r"(a) : "l"(p));
    return a;
}
#define CP16(dst, src) \
    asm volatile("cp.async.cg.shared.global [%0], [%1], 16;" :: "r"((uint32_t)(dst)), "l"(src))
#define CP_COMMIT() asm volatile("cp.async.commit_group;" ::: "memory")
#define CP_WAITN(n) asm volatile("cp.async.wait_group %0;" :: "n"(n) : "memory")

#define LDSM4(r, addr) \
    asm volatile("ldmatrix.sync.aligned.m8n8.x4.shared.b16 {%0,%1,%2,%3}, [%4];" \
        : "=r"((r)[0]), "=r"((r)[1]), "=r"((r)[2]), "=r"((r)[3]) : "r"(addr))
#define LDSM2(r, addr) \
    asm volatile("ldmatrix.sync.aligned.m8n8.x2.shared.b16 {%0,%1}, [%2];" \
        : "=r"((r)[0]), "=r"((r)[1]) : "r"(addr))
#define MMA(d, a, b) \
    asm volatile("mma.sync.aligned.m16n8k16.row.col.f32.bf16.bf16.f32 " \
        "{%0,%1,%2,%3},{%4,%5,%6,%7},{%8,%9},{%0,%1,%2,%3};" \
        : "+f"((d)[0]), "+f"((d)[1]), "+f"((d)[2]), "+f"((d)[3]) \
        : "r"((a)[0]), "r"((a)[1]), "r"((a)[2]), "r"((a)[3]), "r"((b)[0]), "r"((b)[1]))

__device__ __forceinline__ float sigm(float x) { return 1.f / (1.f + __expf(-x)); }
__device__ __forceinline__ float tanh_f(float x) { return 1.f - 2.f / (__expf(2.f * x) + 1.f); }

// ---------------- geometry ----------------
// xw kernel (128 threads, 2-stage, 64x64 tiles)
#define ROWB 272
#define MATB (64 * ROWB)      // 17408
#define BUFB (4 * MATB)       // 69632 (Ah, Al, Bh, Bl)
#define SMEM_XW (2 * BUFB)    // 139264

// persistent step kernel (256 threads): W resident + 2-stage A + staging
#define WROWB 2064                       // 1024 bf16 + 16B pad (odd multiple of 16)
#define WMATB (32 * WROWB)               // 66048
#define W_HI 0
#define W_LO WMATB                       // 66048
#define ASTG (2 * WMATB)                 // 132096
#define ASTGB (2 * MATB)                 // 34816 per stage (hi+lo)
#define GS_OFF (ASTG + 2 * ASTGB)        // 201728 ; Gs = 32 x 68 f32 = 8704
#define HS_OFF (GS_OFF + 8704)           // 210432 ; Hs_hi/lo = 2 * 64*8*2B = 2048
#define SMEM_ST (HS_OFF + 2048)          // 212480

// ---------------- init: zero h and c, reset barrier ----------------
__global__ void init_kernel() {
    int i = blockIdx.x * blockDim.x + threadIdx.x;
    if (i == 0) { g_cnt = 0; g_flag = 0; }
    if (i < Bz * Hz) {
        __nv_bfloat16 z = __float2bfloat16(0.f);
        g_h_hi[0][i] = z; g_h_hi[1][i] = z;
        g_h_lo[0][i] = z; g_h_lo[1][i] = z;
        g_c[i] = 0.f;
    }
}

// ---------------- prep: transpose+split W -> [n'=c*4+g][k] bf16 hi/lo ----------------
__global__ __launch_bounds__(256) void prep_tr(const float* __restrict__ src, int K, int sel) {
    __shared__ float tile[32][33];
    int n0 = blockIdx.x * 32, k0 = blockIdx.y * 32;
    int tx = threadIdx.x & 31, ty = threadIdx.x >> 5;   // 32 x 8
#pragma unroll
    for (int r = 0; r < 4; r++)
        tile[ty + r * 8][tx] = src[(size_t)(k0 + ty + r * 8) * G4 + n0 + tx];
    __syncthreads();
    __nv_bfloat16* dh = sel ? g_wt_hi : g_wx_hi;
    __nv_bfloat16* dl = sel ? g_wt_lo : g_wx_lo;
#pragma unroll
    for (int r = 0; r < 4; r++) {
        int n = n0 + ty + r * 8;
        int np = (n & 1023) * 4 + (n >> 10);
        float v = tile[tx][ty + r * 8];
        __nv_bfloat16 hi = __float2bfloat16(v);
        dh[(size_t)np * K + k0 + tx] = hi;
        dl[(size_t)np * K + k0 + tx] = __float2bfloat16(v - __bfloat162float(hi));
    }
}

// ---------------- prep: gather emb rows, split to bf16 hi/lo [m][k] ----------------
__global__ void prep_emb(const int* __restrict__ X, const float* __restrict__ emb) {
    int m = blockIdx.x;                 // m = s*64+b
    int s = m >> 6, b = m & 63;
    int row = X[b * Sz + s];
    const float4* src = (const float4*)(emb + (size_t)row * Ez);
    int k4 = threadIdx.x;
    float4 v = src[k4];
    __nv_bfloat16 hx = __float2bfloat16(v.x), hy = __float2bfloat16(v.y);
    __nv_bfloat16 hz = __float2bfloat16(v.z), hw = __float2bfloat16(v.w);
    __nv_bfloat162* dh = (__nv_bfloat162*)(g_a_hi + (size_t)m * Ez);
    __nv_bfloat162* dl = (__nv_bfloat162*)(g_a_lo + (size_t)m * Ez);
    dh[k4 * 2]     = __nv_bfloat162(hx, hy);
    dh[k4 * 2 + 1] = __nv_bfloat162(hz, hw);
    dl[k4 * 2]     = __nv_bfloat162(__float2bfloat16(v.x - __bfloat162float(hx)),
                                    __float2bfloat16(v.y - __bfloat162float(hy)));
    dl[k4 * 2 + 1] = __nv_bfloat162(__float2bfloat16(v.z - __bfloat162float(hz)),
                                    __float2bfloat16(v.w - __bfloat162float(hw)));
}

__global__ void prep_bias(const float* __restrict__ bias) {
    int n = blockIdx.x * blockDim.x + threadIdx.x;
    if (n < G4) g_bias2[(n & 1023) * 4 + (n >> 10)] = bias[n];
}

// ---------------- xw GEMM building blocks (128 threads) ----------------
__device__ __forceinline__ void load_mat(uint32_t dst, const __nv_bfloat16* src,
                                         int stride_elems, int tid) {
#pragma unroll
    for (int i = 0; i < 8; i++) {
        int idx = i * 128 + tid;
        int row = idx >> 4, seg = idx & 15;
        CP16(dst + row * ROWB + seg * 16,
             (const char*)(src + (size_t)row * stride_elems) + seg * 16);
    }
}

__device__ __forceinline__ void compute_chunk(uint32_t buf, int lane, int mbase, int nbase,
                                              float acc[2][4][4]) {
    const uint32_t aH = buf, aL = buf + MATB, bH = buf + 2 * MATB, bL = buf + 3 * MATB;
    const int g = lane >> 3;
    const int arow = (lane & 7) + ((g & 1) << 3);
    const int ahalf = (g >> 1) * 16;
    const int brow = lane & 7;
    const int bhalf = ((lane >> 3) & 1) * 16;
#pragma unroll
    for (int k16 = 0; k16 < 8; k16++) {
        const uint32_t kb = k16 * 32;
        uint32_t ah[2][4], al[2][4], bh[4][2], bl[4][2];
#pragma unroll
        for (int mt = 0; mt < 2; mt++) {
            uint32_t ao = (uint32_t)((mbase + mt * 16 + arow) * ROWB) + kb + ahalf;
            LDSM4(ah[mt], aH + ao);
            LDSM4(al[mt], aL + ao);
        }
#pragma unroll
        for (int nt = 0; nt < 4; nt++) {
            uint32_t bo = (uint32_t)((nbase + nt * 8 + brow) * ROWB) + kb + bhalf;
            LDSM2(bh[nt], bH + bo);
            LDSM2(bl[nt], bL + bo);
        }
#pragma unroll
        for (int mt = 0; mt < 2; mt++)
#pragma unroll
            for (int nt = 0; nt < 4; nt++) {
                MMA(acc[mt][nt], ah[mt], bh[nt]);
                MMA(acc[mt][nt], ah[mt], bl[nt]);
                MMA(acc[mt][nt], al[mt], bh[nt]);
            }
    }
}

__device__ __forceinline__ void store_frags_to_Gs(float* Gs, int lane, int mbase, int nbase,
                                                  float acc[2][4][4]) {
    const int r = lane >> 2, c2 = (lane & 3) * 2;
#pragma unroll
    for (int mt = 0; mt < 2; mt++)
#pragma unroll
        for (int nt = 0; nt < 4; nt++) {
            int m = mbase + mt * 16 + r;
            int n = nbase + nt * 8 + c2;
            Gs[n * 68 + m]           = acc[mt][nt][0];
            Gs[(n + 1) * 68 + m]     = acc[mt][nt][1];
            Gs[n * 68 + m + 8]       = acc[mt][nt][2];
            Gs[(n + 1) * 68 + m + 8] = acc[mt][nt][3];
        }
}

// ---------------- xw GEMM: g_xw2[s][n'][b] = emb_m @ Wx^T + bias (bf16x3) ----------------
__global__ __launch_bounds__(128, 1) void xw_mma() {
    extern __shared__ char smem[];
    const uint32_t sb = smem_u32(smem);
    const int tid = threadIdx.x, lane = tid & 31, w = tid >> 5;
    const int np0 = blockIdx.x * 64;
    const int s = blockIdx.y;
    const __nv_bfloat16* Ah = g_a_hi + (size_t)s * Bz * Ez;
    const __nv_bfloat16* Al = g_a_lo + (size_t)s * Bz * Ez;
    const __nv_bfloat16* Bh = g_wx_hi + (size_t)np0 * Ez;
    const __nv_bfloat16* Bl = g_wx_lo + (size_t)np0 * Ez;

    float acc[2][4][4] = {};
    const int mbase = (w & 1) * 32, nbase = (w >> 1) * 32;

    load_mat(sb, Ah, Ez, tid);
    load_mat(sb + MATB, Al, Ez, tid);
    load_mat(sb + 2 * MATB, Bh, Ez, tid);
    load_mat(sb + 3 * MATB, Bl, Ez, tid);
    CP_COMMIT();

    for (int c = 0; c < 4; c++) {
        if (c < 3) {
            int kc = (c + 1) * 128;
            uint32_t buf = sb + ((c + 1) & 1) * BUFB;
            load_mat(buf, Ah + kc, Ez, tid);
            load_mat(buf + MATB, Al + kc, Ez, tid);
            load_mat(buf + 2 * MATB, Bh + kc, Ez, tid);
            load_mat(buf + 3 * MATB, Bl + kc, Ez, tid);
            CP_COMMIT();
            CP_WAITN(1);
        } else {
            CP_WAITN(0);
        }
        __syncthreads();
        compute_chunk(sb + (c & 1) * BUFB, lane, mbase, nbase, acc);
        __syncthreads();
    }

    float* Gs = (float*)smem;   // [64][68]
    store_frags_to_Gs(Gs, lane, mbase, nbase, acc);
    __syncthreads();

    float* outb = g_xw2 + ((size_t)s * G4 + np0) * Bz;
#pragma unroll
    for (int i = 0; i < 32; i++) {
        int e = i * 128 + tid;               // e = n'local*64 + b
        int nl = e >> 6, b = e & 63;
        outb[e] = Gs[nl * 68 + b] + g_bias2[np0 + nl];
    }
}

// ---------------- persistent LSTM recurrence ----------------
// 128 co-resident CTAs x 256 threads. CTA owns 32 n' (8 h-cols). W smem-resident.
__device__ __forceinline__ void gbar_arrive_wait(int target, int tid) {
    __syncthreads();
    if (tid == 0) {
        int old;
        asm volatile("atom.add.acq_rel.gpu.global.s32 %0, [%1], 1;"
                     : "=r"(old) : "l"(&g_cnt) : "memory");
        if (old == 127) {
            g_cnt = 0;
            asm volatile("st.release.gpu.global.s32 [%0], %1;"
                         :: "l"(&g_flag), "r"(target) : "memory");
        } else {
            int f;
            do {
                asm volatile("ld.acquire.gpu.global.s32 %0, [%1];"
                             : "=r"(f) : "l"(&g_flag));
            } while (f < target);
        }
    }
    __syncthreads();
}

// load one 64x128 bf16 A tile (256 threads, 4 CP16 each)
__device__ __forceinline__ void load_A(uint32_t dst, const __nv_bfloat16* src, int tid) {
#pragma unroll
    for (int i = 0; i < 4; i++) {
        int idx = i * 256 + tid;
        int row = idx >> 4, seg = idx & 15;
        CP16(dst + row * ROWB + seg * 16,
             (const char*)(src + (size_t)row * Hz) + seg * 16);
    }
}

__global__ __launch_bounds__(256, 1) void steps_persistent(const int* __restrict__ seqlen) {
    extern __shared__ char smem[];
    const uint32_t sb = smem_u32(smem);
    const int tid = threadIdx.x, lane = tid & 31, w = tid >> 5;
    const int blk = blockIdx.x;
    const int np0 = blk * 32, c0 = blk * 8;
    const int mbase = (w & 3) * 16;      // batch rows
    const int nbase = (w >> 2) * 16;     // n' cols
    const int sl_b = __ldg(seqlen + (tid & 63));

    // ---- load W resident: 32 rows x 1024 k, hi+lo ----
#pragma unroll
    for (int i = 0; i < 16; i++) {
        int idx = i * 256 + tid;
        int row = idx >> 7, seg = idx & 127;
        CP16(sb + W_HI + row * WROWB + seg * 16,
             (const char*)(g_wt_hi + (size_t)(np0 + row) * Hz) + seg * 16);
    }
#pragma unroll
    for (int i = 0; i < 16; i++) {
        int idx = i * 256 + tid;
        int row = idx >> 7, seg = idx & 127;
        CP16(sb + W_LO + row * WROWB + seg * 16,
             (const char*)(g_wt_lo + (size_t)(np0 + row) * Hz) + seg * 16);
    }
    CP_COMMIT();

    float* Gs = (float*)(smem + GS_OFF);                     // [32 n'][68]
    __nv_bfloat16* HsH = (__nv_bfloat16*)(smem + HS_OFF);    // [64][8]
    __nv_bfloat16* HsL = (__nv_bfloat16*)(smem + HS_OFF + 1024);

    for (int t = 0; t < Sz; t++) {
        const __nv_bfloat16* h_hi = g_h_hi[t & 1];
        const __nv_bfloat16* h_lo = g_h_lo[t & 1];
        __nv_bfloat16* o_hi = g_h_hi[(t + 1) & 1];
        __nv_bfloat16* o_lo = g_h_lo[(t + 1) & 1];

        if (t > 0) gbar_arrive_wait(t, tid);                 // all CTAs finished t-1

        // prefetch xw + c for epilogue (independent of MMA)
        const float* xwb = g_xw2 + ((size_t)t * G4 + np0) * Bz;
        float xg[2][4], cold[2];
        {
            const int b = tid & 63;
#pragma unroll
            for (int i = 0; i < 2; i++) {
                int col = (i * 256 + tid) >> 6;
#pragma unroll
                for (int g = 0; g < 4; g++)
                    xg[i][g] = __ldg(xwb + (col * 4 + g) * Bz + b);
                cold[i] = g_c[(c0 + col) * Bz + b];
            }
        }

        // chunk 0 A load
        load_A(sb + ASTG, h_hi, tid);
        load_A(sb + ASTG + MATB, h_lo, tid);
        CP_COMMIT();

        float acc[2][4] = {};                                // [nt][4], warp tile 16x16
#pragma unroll
        for (int c = 0; c < 8; c++) {
            if (c < 7) {
                uint32_t buf = sb + ASTG + (uint32_t)((c + 1) & 1) * ASTGB;
                load_A(buf, h_hi + (c + 1) * 128, tid);
                load_A(buf + MATB, h_lo + (c + 1) * 128, tid);
                CP_COMMIT();
                CP_WAITN(1);
            } else {
                CP_WAITN(0);
            }
            __syncthreads();

            // compute chunk c from stage (c&1) + resident W
            {
                const uint32_t abuf = sb + ASTG + (uint32_t)(c & 1) * ASTGB;
                const int arow = mbase + (lane & 15);
                const int ahalf = (lane >> 4) * 16;
                const int brow = lane & 7;
                const int bhalf = ((lane >> 3) & 1) * 16;
                const uint32_t kwb = (uint32_t)c * 256;      // W k-offset bytes
#pragma unroll
                for (int k16 = 0; k16 < 8; k16++) {
                    uint32_t ah[4], al[4], bh[2][2], bl[2][2];
                    uint32_t ao = (uint32_t)(arow * ROWB) + k16 * 32 + ahalf;
                    LDSM4(ah, abuf + ao);
                    LDSM4(al, abuf + MATB + ao);
#pragma unroll
                    for (int nt = 0; nt < 2; nt++) {
                        uint32_t bo = (uint32_t)((nbase + nt * 8 + brow) * WROWB)
                                      + kwb + k16 * 32 + bhalf;
                        LDSM2(bh[nt], sb + W_HI + bo);
                        LDSM2(bl[nt], sb + W_LO + bo);
                    }
#pragma unroll
                    for (int nt = 0; nt < 2; nt++) {
                        MMA(acc[nt], ah, bh[nt]);
                        MMA(acc[nt], ah, bl[nt]);
                        MMA(acc[nt], al, bh[nt]);
                    }
                }
            }
            __syncthreads();
        }

        // stage gate tile to smem
        {
            const int r = lane >> 2, c2 = (lane & 3) * 2;
#pragma unroll
            for (int nt = 0; nt < 2; nt++) {
                int m = mbase + r;
                int n = nbase + nt * 8 + c2;
                Gs[n * 68 + m]           = acc[nt][0];
                Gs[(n + 1) * 68 + m]     = acc[nt][1];
                Gs[n * 68 + m + 8]       = acc[nt][2];
                Gs[(n + 1) * 68 + m + 8] = acc[nt][3];
            }
        }
        __syncthreads();

        // pointwise LSTM for 8 cols x 64 batch
        const bool is_last = (t == sl_b - 1);
#pragma unroll
        for (int i = 0; i < 2; i++) {
            int e = i * 256 + tid;
            int col = e >> 6, b = e & 63;
            float ig = Gs[(col * 4 + 0) * 68 + b] + xg[i][0];
            float jg = Gs[(col * 4 + 1) * 68 + b] + xg[i][1];
            float fg = Gs[(col * 4 + 2) * 68 + b] + xg[i][2];
            float og = Gs[(col * 4 + 3) * 68 + b] + xg[i][3];
            float cn = cold[i] * sigm(fg + 1.0f) + sigm(ig) * tanh_f(jg);
            float hn = tanh_f(cn) * sigm(og);
            g_c[(c0 + col) * Bz + b] = cn;
            __nv_bfloat16 hi = __float2bfloat16(hn);
            HsH[b * 8 + col] = hi;
            HsL[b * 8 + col] = __float2bfloat16(hn - __bfloat162float(hi));
            if (is_last) g_final[(size_t)b * Hz + c0 + col] = hn;
        }
        __syncthreads();

        // coalesced 16B h writes: 64 threads hi, 64 threads lo
        if (tid < 64) {
            *(uint4*)(o_hi + (size_t)tid * Hz + c0) = *(uint4*)(HsH + tid * 8);
        } else if (tid < 128) {
            int b = tid - 64;
            *(uint4*)(o_lo + (size_t)b * Hz + c0) = *(uint4*)(HsL + b * 8);
        }
    }
}

// ---------------- dense = relu(final @ dense_w + dense_b) ----------------
__global__ void dense_kernel(const float* __restrict__ dw, const float* __restrict__ db) {
    int b = blockIdx.x;
    int d = threadIdx.x;    // 512 threads
    const float* f = g_final + (size_t)b * Hz;
    float s0 = 0.f, s1 = 0.f, s2 = 0.f, s3 = 0.f;
#pragma unroll 4
    for (int k = 0; k < Hz; k += 4) {
        s0 += f[k]     * dw[(size_t)(k)     * Dz + d];
        s1 += f[k + 1] * dw[(size_t)(k + 1) * Dz + d];
        s2 += f[k + 2] * dw[(size_t)(k + 2) * Dz + d];
        s3 += f[k + 3] * dw[(size_t)(k + 3) * Dz + d];
    }
    float s = (s0 + s1) + (s2 + s3) + db[d];
    g_dense[(size_t)b * Dz + d] = fmaxf(s, 0.f);
}

// ---------------- logits = dense @ pred_w + pred_b ----------------
__global__ void logits_kernel(const float* __restrict__ pw, const float* __restrict__ pb,
                              float* __restrict__ out) {
    int tid = threadIdx.x;
    if (tid >= Bz * Cz) return;
    int b = tid >> 1;
    int cc = tid & 1;
    const float* dn = g_dense + (size_t)b * Dz;
    float s = 0.f;
#pragma unroll 4
    for (int d = 0; d < Dz; d++) s += dn[d] * pw[(size_t)d * Cz + cc];
    out[b * Cz + cc] = s + pb[cc];
}

// ---------------- launch ----------------
extern "C" void kernel_launch(void* const* d_in, const int* in_sizes, int n_in,
                              void* d_out, int out_size) {
    const int*   X      = (const int*)d_in[0];
    const int*   seqlen = (const int*)d_in[1];
    const float* emb    = (const float*)d_in[2];
    const float* Wf     = (const float*)d_in[3];   // [1536, 4096]
    const float* bias   = (const float*)d_in[4];
    const float* dw     = (const float*)d_in[5];
    const float* db     = (const float*)d_in[6];
    const float* pw     = (const float*)d_in[7];
    const float* pb     = (const float*)d_in[8];
    float* out = (float*)d_out;

    cudaFuncSetAttribute(xw_mma, cudaFuncAttributeMaxDynamicSharedMemorySize, SMEM_XW);
    cudaFuncSetAttribute(steps_persistent, cudaFuncAttributeMaxDynamicSharedMemorySize, SMEM_ST);

    init_kernel<<<(Bz * Hz + 255) / 256, 256>>>();
    prep_tr<<<dim3(G4 / 32, Ez / 32), 256>>>(Wf, Ez, 0);                   // Wx
    prep_tr<<<dim3(G4 / 32, Hz / 32), 256>>>(Wf + (size_t)Ez * G4, Hz, 1); // Wh
    prep_emb<<<Sz * Bz, 128>>>(X, emb);
    prep_bias<<<G4 / 256, 256>>>(bias);

    xw_mma<<<dim3(G4 / 64, Sz), 128, SMEM_XW>>>();

    steps_persistent<<<128, 256, SMEM_ST>>>(seqlen);

    dense_kernel<<<Bz, Dz>>>(dw, db);
    logits_kernel<<<1, 128>>>(pw, pb, out);
}